// round 6
// baseline (speedup 1.0000x reference)
#include <cuda_runtime.h>
#include <cuda_fp16.h>
#include <math.h>
#include <stdint.h>

#define NN 100000
#define DD 128
#define EE 1600000
#define NB_SCAN 98
#define BN_EPS 1e-5f

// ---------------- helpers ----------------
__device__ __forceinline__ uint32_t smem_u32(const void* p) {
    uint32_t a;
    asm("{ .reg .u64 t; cvta.to.shared.u64 t, %1; cvt.u32.u64 %0, t; }" : "=r"(a) : "l"(p));
    return a;
}
__device__ __forceinline__ void ldsm4(uint32_t* r, uint32_t a) {
    asm volatile("ldmatrix.sync.aligned.m8n8.x4.shared.b16 {%0,%1,%2,%3}, [%4];"
        : "=r"(r[0]), "=r"(r[1]), "=r"(r[2]), "=r"(r[3]) : "r"(a));
}
__device__ __forceinline__ void ldsm4t(uint32_t* r, uint32_t a) {
    asm volatile("ldmatrix.sync.aligned.m8n8.x4.trans.shared.b16 {%0,%1,%2,%3}, [%4];"
        : "=r"(r[0]), "=r"(r[1]), "=r"(r[2]), "=r"(r[3]) : "r"(a));
}
__device__ __forceinline__ void mma_f16(float* c, const uint32_t* a, uint32_t b0, uint32_t b1) {
    asm volatile("mma.sync.aligned.m16n8k16.row.col.f32.f16.f16.f32 "
        "{%0,%1,%2,%3}, {%4,%5,%6,%7}, {%8,%9}, {%0,%1,%2,%3};"
        : "+f"(c[0]), "+f"(c[1]), "+f"(c[2]), "+f"(c[3])
        : "r"(a[0]), "r"(a[1]), "r"(a[2]), "r"(a[3]), "r"(b0), "r"(b1));
}

// ---------------- device scratch ----------------
__device__ __align__(16) __half g_h16[NN * DD];   // GEMM out / SpMM gather src
__device__ __align__(16) __half g_a16[NN * DD];   // SpMM out / GEMM in (layers 1,2)
__device__ int   g_cnt[NN];
__device__ int   g_rptr[NN + 1];
__device__ int   g_part[128];
__device__ int   g_part2[128];
__device__ __align__(8) int2 g_edge[EE];          // {col, w-bits}
__device__ float g_sum[2][DD];
__device__ float g_sq[2][DD];
__device__ float g_scale[DD];
__device__ float g_shift[DD];
// W images: [layer][hi/lo][k:128][n:136 padded] fp16
__device__ __align__(16) __half g_wimg[3][2][128][136];

// ---------------- CSR build ----------------
__global__ void k_zero_cnt() {
    int i = blockIdx.x * blockDim.x + threadIdx.x;
    if (i < NN) g_cnt[i] = 0;
    if (i < 2 * DD) { (&g_sum[0][0])[i] = 0.f; (&g_sq[0][0])[i] = 0.f; }
}
__global__ void k_count(const int* __restrict__ row) {
    int e = blockIdx.x * blockDim.x + threadIdx.x;
    if (e < EE) atomicAdd(&g_cnt[row[e]], 1);
}
__global__ __launch_bounds__(1024) void k_scan1() {
    __shared__ int s[1024];
    int t = threadIdx.x;
    int i = blockIdx.x * 1024 + t;
    int v = (i < NN) ? g_cnt[i] : 0;
    s[t] = v;
    #pragma unroll
    for (int off = 1; off < 1024; off <<= 1) {
        __syncthreads();
        int x = (t >= off) ? s[t - off] : 0;
        __syncthreads();
        s[t] += x;
    }
    int incl = s[t];
    if (i < NN) g_rptr[i] = incl - v;
    if (t == 1023) g_part[blockIdx.x] = incl;
}
__global__ void k_scan2(int nb) {
    __shared__ int s[128];
    int t = threadIdx.x;
    int v = (t < nb) ? g_part[t] : 0;
    s[t] = v;
    #pragma unroll
    for (int off = 1; off < 128; off <<= 1) {
        __syncthreads();
        int x = (t >= off) ? s[t - off] : 0;
        __syncthreads();
        s[t] += x;
    }
    g_part2[t] = s[t] - v;
}
__global__ void k_scan3() {
    int i = blockIdx.x * blockDim.x + threadIdx.x;
    if (i < NN) {
        int v = g_rptr[i] + g_part2[i >> 10];
        g_rptr[i] = v;
        g_cnt[i] = v;
    }
    if (i == 0) g_rptr[NN] = EE;
}
__global__ void k_fill(const int* __restrict__ row, const int* __restrict__ col,
                       const float* __restrict__ ew) {
    int e = blockIdx.x * blockDim.x + threadIdx.x;
    if (e < EE) {
        int r = row[e];
        int p = atomicAdd(&g_cnt[r], 1);
        g_edge[p] = make_int2(col[e], __float_as_int(ew[e]));
    }
}

// ---------------- W prep: fp16 hi/lo split, [k][n] layout ----------------
__global__ void k_wprep(const float* __restrict__ W0, const float* __restrict__ W1,
                        const float* __restrict__ W2) {
    int l = blockIdx.x / 128;
    int k = blockIdx.x % 128;
    int n = threadIdx.x;
    const float* W = (l == 0) ? W0 : (l == 1) ? W1 : W2;
    float w = W[k * 128 + n];
    __half hi = __float2half_rn(w);
    __half lo = __float2half_rn(w - __half2float(hi));
    g_wimg[l][0][k][n] = hi;
    g_wimg[l][1][k][n] = lo;
}

// ---------------- layer-0 GEMM: fp32 input, fp16x3 split ----------------
#define GEMM_SMEM (18432 * 2 + 17408 * 2)

__global__ __launch_bounds__(256) void k_gemm_tc(
    const float* __restrict__ A, int layer,
    const float* __restrict__ bias,
    __half* __restrict__ out16, int M)
{
    extern __shared__ char sm[];
    __half* sAh = (__half*)sm;              // [128][72]
    __half* sAl = (__half*)(sm + 18432);
    int t = threadIdx.x, lane = t & 31, wid = t >> 5;
    int m0 = blockIdx.x * 128;
    int m_warp = (wid & 1) * 64;
    int n_warp = (wid >> 1) * 32;

    uint32_t sbase = smem_u32(sm);
    uint32_t aAddrH = sbase + (uint32_t)(((m_warp + (lane & 15)) * 72 + (lane >> 4) * 8) * 2);
    uint32_t aAddrL = aAddrH + 18432;
    uint32_t wAddrH = sbase + 36864u + (uint32_t)(((lane & 15) * 136 + n_warp + (lane >> 4) * 8) * 2);
    uint32_t wAddrL = wAddrH + 17408;

    float acc[4][4][4] = {};

    for (int ch = 0; ch < 2; ch++) {
        const float4* whi = (const float4*)&g_wimg[layer][0][ch * 64][0];
        const float4* wlo = (const float4*)&g_wimg[layer][1][ch * 64][0];
        float4* dWh = (float4*)(sm + 36864);
        float4* dWl = (float4*)(sm + 54272);
        #pragma unroll
        for (int i = 0; i < 5; i++) {
            int idx = t + i * 256;
            if (idx < 1088) { dWh[idx] = whi[idx]; dWl[idx] = wlo[idx]; }
        }
        #pragma unroll
        for (int i = 0; i < 8; i++) {
            int idx = t + i * 256;
            int r = idx >> 4, kq = idx & 15;
            int gr = m0 + r;
            float4 v = make_float4(0.f, 0.f, 0.f, 0.f);
            if (gr < M) v = *(const float4*)(A + gr * 128 + ch * 64 + kq * 4);
            __half hx = __float2half_rn(v.x), hy = __float2half_rn(v.y);
            __half hz = __float2half_rn(v.z), hw = __float2half_rn(v.w);
            __half2 h01 = __halves2half2(hx, hy), h23 = __halves2half2(hz, hw);
            __half2 l01 = __floats2half2_rn(v.x - __half2float(hx), v.y - __half2float(hy));
            __half2 l23 = __floats2half2_rn(v.z - __half2float(hz), v.w - __half2float(hw));
            uint2 uh, ul;
            uh.x = *(uint32_t*)&h01; uh.y = *(uint32_t*)&h23;
            ul.x = *(uint32_t*)&l01; ul.y = *(uint32_t*)&l23;
            *(uint2*)&sAh[r * 72 + kq * 4] = uh;
            *(uint2*)&sAl[r * 72 + kq * 4] = ul;
        }
        __syncthreads();

        #pragma unroll
        for (int ks = 0; ks < 4; ks++) {
            int k0 = ks * 16;
            uint32_t Ah[4][4], Al[4][4], Wh[2][4], Wl[2][4];
            #pragma unroll
            for (int mt = 0; mt < 4; mt++) {
                uint32_t off = (uint32_t)((mt * 16 * 72 + k0) * 2);
                ldsm4(Ah[mt], aAddrH + off);
                ldsm4(Al[mt], aAddrL + off);
            }
            #pragma unroll
            for (int ng = 0; ng < 2; ng++) {
                uint32_t off = (uint32_t)((k0 * 136 + ng * 16) * 2);
                ldsm4t(Wh[ng], wAddrH + off);
                ldsm4t(Wl[ng], wAddrL + off);
            }
            #pragma unroll
            for (int mt = 0; mt < 4; mt++)
                #pragma unroll
                for (int nt = 0; nt < 4; nt++) {
                    int ng = nt >> 1, s = (nt & 1) * 2;
                    mma_f16(acc[mt][nt], Ah[mt], Wh[ng][s], Wh[ng][s + 1]);
                    mma_f16(acc[mt][nt], Ah[mt], Wl[ng][s], Wl[ng][s + 1]);
                    mma_f16(acc[mt][nt], Al[mt], Wh[ng][s], Wh[ng][s + 1]);
                }
        }
        __syncthreads();
    }

    #pragma unroll
    for (int mt = 0; mt < 4; mt++) {
        int r0 = m0 + m_warp + mt * 16 + (lane >> 2);
        #pragma unroll
        for (int nt = 0; nt < 4; nt++) {
            int col = n_warp + nt * 8 + (lane & 3) * 2;
            float b0 = bias[col], b1 = bias[col + 1];
            if (r0 < M) {
                __half2 o = __floats2half2_rn(acc[mt][nt][0] + b0, acc[mt][nt][1] + b1);
                *(__half2*)(out16 + r0 * 128 + col) = o;
            }
            if (r0 + 8 < M) {
                __half2 o = __floats2half2_rn(acc[mt][nt][2] + b0, acc[mt][nt][3] + b1);
                *(__half2*)(out16 + (r0 + 8) * 128 + col) = o;
            }
        }
    }
}

// ---------------- layers 1-2 GEMM: fp16 input + BN/ReLU, 2-term MMA ----------------
#define GEMMH_SMEM (18432 + 17408 * 2)

__global__ __launch_bounds__(256) void k_gemm_tc_h(
    const __half* __restrict__ A, int layer,
    const float* __restrict__ bias,
    __half* __restrict__ out16, int M)
{
    extern __shared__ char sm[];
    __half* sAh = (__half*)sm;              // [128][72]
    int t = threadIdx.x, lane = t & 31, wid = t >> 5;
    int m0 = blockIdx.x * 128;
    int m_warp = (wid & 1) * 64;
    int n_warp = (wid >> 1) * 32;

    uint32_t sbase = smem_u32(sm);
    uint32_t aAddrH = sbase + (uint32_t)(((m_warp + (lane & 15)) * 72 + (lane >> 4) * 8) * 2);
    uint32_t wAddrH = sbase + 18432u + (uint32_t)(((lane & 15) * 136 + n_warp + (lane >> 4) * 8) * 2);
    uint32_t wAddrL = wAddrH + 17408;

    float acc[4][4][4] = {};

    for (int ch = 0; ch < 2; ch++) {
        const float4* whi = (const float4*)&g_wimg[layer][0][ch * 64][0];
        const float4* wlo = (const float4*)&g_wimg[layer][1][ch * 64][0];
        float4* dWh = (float4*)(sm + 18432);
        float4* dWl = (float4*)(sm + 35840);
        #pragma unroll
        for (int i = 0; i < 5; i++) {
            int idx = t + i * 256;
            if (idx < 1088) { dWh[idx] = whi[idx]; dWl[idx] = wlo[idx]; }
        }
        // A chunk: 128 rows x 64 halves = 1024 uint4
        #pragma unroll
        for (int i = 0; i < 4; i++) {
            int idx = t + i * 256;
            int r = idx >> 3, kq = idx & 7;
            int gr = m0 + r;
            uint4 raw = make_uint4(0u, 0u, 0u, 0u);
            if (gr < M) raw = *(const uint4*)(A + gr * 128 + ch * 64 + kq * 8);
            int kg = ch * 64 + kq * 8;
            uint32_t* rr = &raw.x;
            uint4 outv;
            uint32_t* ov = &outv.x;
            #pragma unroll
            for (int q = 0; q < 4; q++) {
                float2 f = __half22float2(*(__half2*)&rr[q]);
                f.x = fmaxf(0.f, fmaf(f.x, g_scale[kg + q * 2 + 0], g_shift[kg + q * 2 + 0]));
                f.y = fmaxf(0.f, fmaf(f.y, g_scale[kg + q * 2 + 1], g_shift[kg + q * 2 + 1]));
                __half2 h = __floats2half2_rn(f.x, f.y);
                ov[q] = *(uint32_t*)&h;
            }
            *(uint4*)&sAh[r * 72 + kq * 8] = outv;
        }
        __syncthreads();

        #pragma unroll
        for (int ks = 0; ks < 4; ks++) {
            int k0 = ks * 16;
            uint32_t Ah[4][4], Wh[2][4], Wl[2][4];
            #pragma unroll
            for (int mt = 0; mt < 4; mt++) {
                uint32_t off = (uint32_t)((mt * 16 * 72 + k0) * 2);
                ldsm4(Ah[mt], aAddrH + off);
            }
            #pragma unroll
            for (int ng = 0; ng < 2; ng++) {
                uint32_t off = (uint32_t)((k0 * 136 + ng * 16) * 2);
                ldsm4t(Wh[ng], wAddrH + off);
                ldsm4t(Wl[ng], wAddrL + off);
            }
            #pragma unroll
            for (int mt = 0; mt < 4; mt++)
                #pragma unroll
                for (int nt = 0; nt < 4; nt++) {
                    int ng = nt >> 1, s = (nt & 1) * 2;
                    mma_f16(acc[mt][nt], Ah[mt], Wh[ng][s], Wh[ng][s + 1]);
                    mma_f16(acc[mt][nt], Ah[mt], Wl[ng][s], Wl[ng][s + 1]);
                }
        }
        __syncthreads();
    }

    #pragma unroll
    for (int mt = 0; mt < 4; mt++) {
        int r0 = m0 + m_warp + mt * 16 + (lane >> 2);
        #pragma unroll
        for (int nt = 0; nt < 4; nt++) {
            int col = n_warp + nt * 8 + (lane & 3) * 2;
            float b0 = bias[col], b1 = bias[col + 1];
            if (r0 < M) {
                __half2 o = __floats2half2_rn(acc[mt][nt][0] + b0, acc[mt][nt][1] + b1);
                *(__half2*)(out16 + r0 * 128 + col) = o;
            }
            if (r0 + 8 < M) {
                __half2 o = __floats2half2_rn(acc[mt][nt][2] + b0, acc[mt][nt][3] + b1);
                *(__half2*)(out16 + (r0 + 8) * 128 + col) = o;
            }
        }
    }
}

// ---------------- SpMM gather (fp16 rows, direct edge loads) + fused BN stats ----------------
__global__ __launch_bounds__(256) void k_spmm4(const uint4* __restrict__ h16,
                                               uint4* __restrict__ o16,
                                               float4* __restrict__ o32,
                                               int statSlot, int outHalf)
{
    __shared__ float ssum[DD];
    __shared__ float ssq[DD];
    int t = threadIdx.x;
    if (statSlot >= 0) {
        if (t < DD) { ssum[t] = 0.f; ssq[t] = 0.f; }
        __syncthreads();
    }
    int lane = t & 31;
    int hw = lane >> 4;       // half-warp id
    int sl = lane & 15;       // slot: covers cols 8*sl..8*sl+7
    int gw = (blockIdx.x * 256 + t) >> 5;
    int nw = (gridDim.x * 256) >> 5;

    float as[8] = {}, aq[8] = {};

    for (int r = gw; r < NN; r += nw) {
        int jb = g_rptr[r], je = g_rptr[r + 1];
        float acc[8] = {};
        // 8 edges per group: 4 per half-warp (broadcast edge loads), 4 gathers in flight
        for (int j = jb; j < je; j += 8) {
            int cc[4]; float ww[4]; uint4 hv[4];
            #pragma unroll
            for (int u = 0; u < 4; u++) {
                int idx = j + u * 2 + hw;
                int2 e = make_int2(0, 0);
                if (idx < je) e = g_edge[idx];
                cc[u] = e.x;
                ww[u] = __int_as_float(e.y);
            }
            #pragma unroll
            for (int u = 0; u < 4; u++)
                hv[u] = h16[cc[u] * 16 + sl];
            #pragma unroll
            for (int u = 0; u < 4; u++) {
                float2 f0 = __half22float2(*(__half2*)&hv[u].x);
                float2 f1 = __half22float2(*(__half2*)&hv[u].y);
                float2 f2 = __half22float2(*(__half2*)&hv[u].z);
                float2 f3 = __half22float2(*(__half2*)&hv[u].w);
                acc[0] = fmaf(ww[u], f0.x, acc[0]);
                acc[1] = fmaf(ww[u], f0.y, acc[1]);
                acc[2] = fmaf(ww[u], f1.x, acc[2]);
                acc[3] = fmaf(ww[u], f1.y, acc[3]);
                acc[4] = fmaf(ww[u], f2.x, acc[4]);
                acc[5] = fmaf(ww[u], f2.y, acc[5]);
                acc[6] = fmaf(ww[u], f3.x, acc[6]);
                acc[7] = fmaf(ww[u], f3.y, acc[7]);
            }
        }
        // combine half-warps
        #pragma unroll
        for (int k = 0; k < 8; k++)
            acc[k] += __shfl_xor_sync(0xffffffffu, acc[k], 16);
        if (lane < 16) {
            if (outHalf) {
                uint4 ov;
                uint32_t* o = &ov.x;
                #pragma unroll
                for (int q = 0; q < 4; q++) {
                    __half2 h = __floats2half2_rn(acc[q * 2], acc[q * 2 + 1]);
                    o[q] = *(uint32_t*)&h;
                }
                o16[r * 16 + sl] = ov;
            } else {
                o32[r * 32 + sl * 2 + 0] = make_float4(acc[0], acc[1], acc[2], acc[3]);
                o32[r * 32 + sl * 2 + 1] = make_float4(acc[4], acc[5], acc[6], acc[7]);
            }
            if (statSlot >= 0) {
                #pragma unroll
                for (int k = 0; k < 8; k++) {
                    as[k] += acc[k];
                    aq[k] = fmaf(acc[k], acc[k], aq[k]);
                }
            }
        }
    }
    if (statSlot >= 0) {
        if (lane < 16) {
            #pragma unroll
            for (int k = 0; k < 8; k++) {
                atomicAdd(&ssum[sl * 8 + k], as[k]);
                atomicAdd(&ssq[sl * 8 + k], aq[k]);
            }
        }
        __syncthreads();
        if (t < DD) {
            atomicAdd(&g_sum[statSlot][t], ssum[t]);
            atomicAdd(&g_sq[statSlot][t], ssq[t]);
        }
    }
}

// ---------------- BN params ----------------
__global__ void k_bnparams(const float* __restrict__ gamma, const float* __restrict__ beta,
                           int slot) {
    int t = threadIdx.x;
    if (t >= DD) return;
    float invn = 1.0f / (float)NN;
    float m = g_sum[slot][t] * invn;
    float v = g_sq[slot][t] * invn - m * m;
    float sc = gamma[t] * rsqrtf(v + BN_EPS);
    g_scale[t] = sc;
    g_shift[t] = beta[t] - sc * m;
}

// ---------------- launch ----------------
extern "C" void kernel_launch(void* const* d_in, const int* in_sizes, int n_in,
                              void* d_out, int out_size) {
    (void)in_sizes; (void)n_in; (void)out_size;
    const float* x  = (const float*)d_in[0];
    const float* ew = (const float*)d_in[1];
    const float* W0 = (const float*)d_in[2];
    const float* b0 = (const float*)d_in[3];
    const float* g0 = (const float*)d_in[4];
    const float* be0= (const float*)d_in[5];
    const float* W1 = (const float*)d_in[6];
    const float* b1 = (const float*)d_in[7];
    const float* g1 = (const float*)d_in[8];
    const float* be1= (const float*)d_in[9];
    const float* W2 = (const float*)d_in[10];
    const float* b2 = (const float*)d_in[11];
    const int* row  = (const int*)d_in[12];
    const int* col  = (const int*)d_in[13];
    float* out = (float*)d_out;

    __half *pH, *pA;
    cudaGetSymbolAddress((void**)&pH, g_h16);
    cudaGetSymbolAddress((void**)&pA, g_a16);

    static cudaStream_t s_csr = nullptr;
    static cudaEvent_t e_fork = nullptr, e_join = nullptr;
    if (s_csr == nullptr) {
        cudaStreamCreateWithFlags(&s_csr, cudaStreamNonBlocking);
        cudaEventCreateWithFlags(&e_fork, cudaEventDisableTiming);
        cudaEventCreateWithFlags(&e_join, cudaEventDisableTiming);
        cudaFuncSetAttribute(k_gemm_tc, cudaFuncAttributeMaxDynamicSharedMemorySize, GEMM_SMEM);
        cudaFuncSetAttribute(k_gemm_tc_h, cudaFuncAttributeMaxDynamicSharedMemorySize, GEMMH_SMEM);
    }

    int gb256_N = (NN + 255) / 256;
    int gb256_E = (EE + 255) / 256;
    int gemm_blocks = (NN + 127) / 128;
    int spmm_blocks = 1184;

    // fork: CSR build + stats zero overlap with W prep + layer-0 GEMM
    cudaEventRecord(e_fork, 0);
    cudaStreamWaitEvent(s_csr, e_fork, 0);
    k_zero_cnt<<<gb256_N, 256, 0, s_csr>>>();
    k_count<<<gb256_E, 256, 0, s_csr>>>(row);
    k_scan1<<<NB_SCAN, 1024, 0, s_csr>>>();
    k_scan2<<<1, 128, 0, s_csr>>>(NB_SCAN);
    k_scan3<<<gb256_N, 256, 0, s_csr>>>();
    k_fill<<<gb256_E, 256, 0, s_csr>>>(row, col, ew);
    cudaEventRecord(e_join, s_csr);

    // main stream: layer 0 GEMM (fp32 x, 3-term)
    k_wprep<<<3 * 128, 128>>>(W0, W1, W2);
    k_gemm_tc<<<gemm_blocks, 256, GEMM_SMEM>>>(x, 0, b0, pH, NN);

    // join CSR before SpMM
    cudaStreamWaitEvent(0, e_join, 0);

    k_spmm4<<<spmm_blocks, 256>>>((const uint4*)pH, (uint4*)pA, nullptr, 0, 1);
    k_bnparams<<<1, 128>>>(g0, be0, 0);

    // layer 1
    k_gemm_tc_h<<<gemm_blocks, 256, GEMMH_SMEM>>>(pA, 1, b1, pH, NN);
    k_spmm4<<<spmm_blocks, 256>>>((const uint4*)pH, (uint4*)pA, nullptr, 1, 1);
    k_bnparams<<<1, 128>>>(g1, be1, 1);

    // layer 2 (no stats, fp32 out)
    k_gemm_tc_h<<<gemm_blocks, 256, GEMMH_SMEM>>>(pA, 2, b2, pH, NN);
    k_spmm4<<<spmm_blocks, 256>>>((const uint4*)pH, nullptr, (float4*)out, -1, 0);
}

// round 7
// speedup vs baseline: 1.1034x; 1.1034x over previous
#include <cuda_runtime.h>
#include <cuda_fp16.h>
#include <math.h>
#include <stdint.h>

#define NN 100000
#define DD 128
#define EE 1600000
#define NB_SCAN 98
#define BN_EPS 1e-5f

// ---------------- helpers ----------------
__device__ __forceinline__ uint32_t smem_u32(const void* p) {
    uint32_t a;
    asm("{ .reg .u64 t; cvta.to.shared.u64 t, %1; cvt.u32.u64 %0, t; }" : "=r"(a) : "l"(p));
    return a;
}
__device__ __forceinline__ void ldsm4(uint32_t* r, uint32_t a) {
    asm volatile("ldmatrix.sync.aligned.m8n8.x4.shared.b16 {%0,%1,%2,%3}, [%4];"
        : "=r"(r[0]), "=r"(r[1]), "=r"(r[2]), "=r"(r[3]) : "r"(a));
}
__device__ __forceinline__ void ldsm4t(uint32_t* r, uint32_t a) {
    asm volatile("ldmatrix.sync.aligned.m8n8.x4.trans.shared.b16 {%0,%1,%2,%3}, [%4];"
        : "=r"(r[0]), "=r"(r[1]), "=r"(r[2]), "=r"(r[3]) : "r"(a));
}
__device__ __forceinline__ void mma_f16(float* c, const uint32_t* a, uint32_t b0, uint32_t b1) {
    asm volatile("mma.sync.aligned.m16n8k16.row.col.f32.f16.f16.f32 "
        "{%0,%1,%2,%3}, {%4,%5,%6,%7}, {%8,%9}, {%0,%1,%2,%3};"
        : "+f"(c[0]), "+f"(c[1]), "+f"(c[2]), "+f"(c[3])
        : "r"(a[0]), "r"(a[1]), "r"(a[2]), "r"(a[3]), "r"(b0), "r"(b1));
}

// ---------------- device scratch ----------------
__device__ __align__(16) __half g_h16[NN * DD];   // GEMM out / SpMM gather src
__device__ __align__(16) __half g_a16[NN * DD];   // SpMM out / GEMM in (layers 1,2)
__device__ int   g_cnt[NN];
__device__ int   g_rptr[NN + 1];
__device__ int   g_part[128];
__device__ int   g_part2[128];
__device__ __align__(8) int2 g_edge[EE];          // {col, w-bits}
__device__ float g_sum[2][DD];
__device__ float g_sq[2][DD];
__device__ float g_scale[DD];
__device__ float g_shift[DD];
// W images: [layer][hi/lo][k:128][n:136 padded] fp16
__device__ __align__(16) __half g_wimg[3][2][128][136];

// ---------------- CSR build ----------------
__global__ void k_zero_cnt() {
    int i = blockIdx.x * blockDim.x + threadIdx.x;
    if (i < NN) g_cnt[i] = 0;
    if (i < 2 * DD) { (&g_sum[0][0])[i] = 0.f; (&g_sq[0][0])[i] = 0.f; }
}
__global__ void k_count(const int* __restrict__ row) {
    int e = blockIdx.x * blockDim.x + threadIdx.x;
    if (e < EE) atomicAdd(&g_cnt[row[e]], 1);
}
__global__ __launch_bounds__(1024) void k_scan1() {
    __shared__ int s[1024];
    int t = threadIdx.x;
    int i = blockIdx.x * 1024 + t;
    int v = (i < NN) ? g_cnt[i] : 0;
    s[t] = v;
    #pragma unroll
    for (int off = 1; off < 1024; off <<= 1) {
        __syncthreads();
        int x = (t >= off) ? s[t - off] : 0;
        __syncthreads();
        s[t] += x;
    }
    int incl = s[t];
    if (i < NN) g_rptr[i] = incl - v;
    if (t == 1023) g_part[blockIdx.x] = incl;
}
__global__ void k_scan2(int nb) {
    __shared__ int s[128];
    int t = threadIdx.x;
    int v = (t < nb) ? g_part[t] : 0;
    s[t] = v;
    #pragma unroll
    for (int off = 1; off < 128; off <<= 1) {
        __syncthreads();
        int x = (t >= off) ? s[t - off] : 0;
        __syncthreads();
        s[t] += x;
    }
    g_part2[t] = s[t] - v;
}
__global__ void k_scan3() {
    int i = blockIdx.x * blockDim.x + threadIdx.x;
    if (i < NN) {
        int v = g_rptr[i] + g_part2[i >> 10];
        g_rptr[i] = v;
        g_cnt[i] = v;
    }
    if (i == 0) g_rptr[NN] = EE;
}
__global__ void k_fill(const int* __restrict__ row, const int* __restrict__ col,
                       const float* __restrict__ ew) {
    int e = blockIdx.x * blockDim.x + threadIdx.x;
    if (e < EE) {
        int r = row[e];
        int p = atomicAdd(&g_cnt[r], 1);
        g_edge[p] = make_int2(col[e], __float_as_int(ew[e]));
    }
}

// ---------------- W prep: fp16 hi/lo split, [k][n] layout ----------------
__global__ void k_wprep(const float* __restrict__ W0, const float* __restrict__ W1,
                        const float* __restrict__ W2) {
    int l = blockIdx.x / 128;
    int k = blockIdx.x % 128;
    int n = threadIdx.x;
    const float* W = (l == 0) ? W0 : (l == 1) ? W1 : W2;
    float w = W[k * 128 + n];
    __half hi = __float2half_rn(w);
    __half lo = __float2half_rn(w - __half2float(hi));
    g_wimg[l][0][k][n] = hi;
    g_wimg[l][1][k][n] = lo;
}

// ---------------- layer-0 GEMM: fp32 input, fp16x3 split ----------------
#define GEMM_SMEM (18432 * 2 + 17408 * 2)

__global__ __launch_bounds__(256) void k_gemm_tc(
    const float* __restrict__ A, int layer,
    const float* __restrict__ bias,
    __half* __restrict__ out16, int M)
{
    extern __shared__ char sm[];
    __half* sAh = (__half*)sm;              // [128][72]
    __half* sAl = (__half*)(sm + 18432);
    int t = threadIdx.x, lane = t & 31, wid = t >> 5;
    int m0 = blockIdx.x * 128;
    int m_warp = (wid & 1) * 64;
    int n_warp = (wid >> 1) * 32;

    uint32_t sbase = smem_u32(sm);
    uint32_t aAddrH = sbase + (uint32_t)(((m_warp + (lane & 15)) * 72 + (lane >> 4) * 8) * 2);
    uint32_t aAddrL = aAddrH + 18432;
    uint32_t wAddrH = sbase + 36864u + (uint32_t)(((lane & 15) * 136 + n_warp + (lane >> 4) * 8) * 2);
    uint32_t wAddrL = wAddrH + 17408;

    float acc[4][4][4] = {};

    for (int ch = 0; ch < 2; ch++) {
        const float4* whi = (const float4*)&g_wimg[layer][0][ch * 64][0];
        const float4* wlo = (const float4*)&g_wimg[layer][1][ch * 64][0];
        float4* dWh = (float4*)(sm + 36864);
        float4* dWl = (float4*)(sm + 54272);
        #pragma unroll
        for (int i = 0; i < 5; i++) {
            int idx = t + i * 256;
            if (idx < 1088) { dWh[idx] = whi[idx]; dWl[idx] = wlo[idx]; }
        }
        #pragma unroll
        for (int i = 0; i < 8; i++) {
            int idx = t + i * 256;
            int r = idx >> 4, kq = idx & 15;
            int gr = m0 + r;
            float4 v = make_float4(0.f, 0.f, 0.f, 0.f);
            if (gr < M) v = *(const float4*)(A + gr * 128 + ch * 64 + kq * 4);
            __half hx = __float2half_rn(v.x), hy = __float2half_rn(v.y);
            __half hz = __float2half_rn(v.z), hw = __float2half_rn(v.w);
            __half2 h01 = __halves2half2(hx, hy), h23 = __halves2half2(hz, hw);
            __half2 l01 = __floats2half2_rn(v.x - __half2float(hx), v.y - __half2float(hy));
            __half2 l23 = __floats2half2_rn(v.z - __half2float(hz), v.w - __half2float(hw));
            uint2 uh, ul;
            uh.x = *(uint32_t*)&h01; uh.y = *(uint32_t*)&h23;
            ul.x = *(uint32_t*)&l01; ul.y = *(uint32_t*)&l23;
            *(uint2*)&sAh[r * 72 + kq * 4] = uh;
            *(uint2*)&sAl[r * 72 + kq * 4] = ul;
        }
        __syncthreads();

        #pragma unroll
        for (int ks = 0; ks < 4; ks++) {
            int k0 = ks * 16;
            uint32_t Ah[4][4], Al[4][4], Wh[2][4], Wl[2][4];
            #pragma unroll
            for (int mt = 0; mt < 4; mt++) {
                uint32_t off = (uint32_t)((mt * 16 * 72 + k0) * 2);
                ldsm4(Ah[mt], aAddrH + off);
                ldsm4(Al[mt], aAddrL + off);
            }
            #pragma unroll
            for (int ng = 0; ng < 2; ng++) {
                uint32_t off = (uint32_t)((k0 * 136 + ng * 16) * 2);
                ldsm4t(Wh[ng], wAddrH + off);
                ldsm4t(Wl[ng], wAddrL + off);
            }
            #pragma unroll
            for (int mt = 0; mt < 4; mt++)
                #pragma unroll
                for (int nt = 0; nt < 4; nt++) {
                    int ng = nt >> 1, s = (nt & 1) * 2;
                    mma_f16(acc[mt][nt], Ah[mt], Wh[ng][s], Wh[ng][s + 1]);
                    mma_f16(acc[mt][nt], Ah[mt], Wl[ng][s], Wl[ng][s + 1]);
                    mma_f16(acc[mt][nt], Al[mt], Wh[ng][s], Wh[ng][s + 1]);
                }
        }
        __syncthreads();
    }

    #pragma unroll
    for (int mt = 0; mt < 4; mt++) {
        int r0 = m0 + m_warp + mt * 16 + (lane >> 2);
        #pragma unroll
        for (int nt = 0; nt < 4; nt++) {
            int col = n_warp + nt * 8 + (lane & 3) * 2;
            float b0 = bias[col], b1 = bias[col + 1];
            if (r0 < M) {
                __half2 o = __floats2half2_rn(acc[mt][nt][0] + b0, acc[mt][nt][1] + b1);
                *(__half2*)(out16 + r0 * 128 + col) = o;
            }
            if (r0 + 8 < M) {
                __half2 o = __floats2half2_rn(acc[mt][nt][2] + b0, acc[mt][nt][3] + b1);
                *(__half2*)(out16 + (r0 + 8) * 128 + col) = o;
            }
        }
    }
}

// ---------------- layers 1-2 GEMM: fp16 input + BN/ReLU, 2-term MMA ----------------
#define GEMMH_SMEM (18432 + 17408 * 2)

__global__ __launch_bounds__(256) void k_gemm_tc_h(
    const __half* __restrict__ A, int layer,
    const float* __restrict__ bias,
    __half* __restrict__ out16, int M)
{
    extern __shared__ char sm[];
    __half* sAh = (__half*)sm;              // [128][72]
    int t = threadIdx.x, lane = t & 31, wid = t >> 5;
    int m0 = blockIdx.x * 128;
    int m_warp = (wid & 1) * 64;
    int n_warp = (wid >> 1) * 32;

    uint32_t sbase = smem_u32(sm);
    uint32_t aAddrH = sbase + (uint32_t)(((m_warp + (lane & 15)) * 72 + (lane >> 4) * 8) * 2);
    uint32_t wAddrH = sbase + 18432u + (uint32_t)(((lane & 15) * 136 + n_warp + (lane >> 4) * 8) * 2);
    uint32_t wAddrL = wAddrH + 17408;

    float acc[4][4][4] = {};

    for (int ch = 0; ch < 2; ch++) {
        const float4* whi = (const float4*)&g_wimg[layer][0][ch * 64][0];
        const float4* wlo = (const float4*)&g_wimg[layer][1][ch * 64][0];
        float4* dWh = (float4*)(sm + 18432);
        float4* dWl = (float4*)(sm + 35840);
        #pragma unroll
        for (int i = 0; i < 5; i++) {
            int idx = t + i * 256;
            if (idx < 1088) { dWh[idx] = whi[idx]; dWl[idx] = wlo[idx]; }
        }
        // A chunk: 128 rows x 64 halves = 1024 uint4
        #pragma unroll
        for (int i = 0; i < 4; i++) {
            int idx = t + i * 256;
            int r = idx >> 3, kq = idx & 7;
            int gr = m0 + r;
            uint4 raw = make_uint4(0u, 0u, 0u, 0u);
            if (gr < M) raw = *(const uint4*)(A + gr * 128 + ch * 64 + kq * 8);
            int kg = ch * 64 + kq * 8;
            uint32_t* rr = &raw.x;
            uint4 outv;
            uint32_t* ov = &outv.x;
            #pragma unroll
            for (int q = 0; q < 4; q++) {
                float2 f = __half22float2(*(__half2*)&rr[q]);
                f.x = fmaxf(0.f, fmaf(f.x, g_scale[kg + q * 2 + 0], g_shift[kg + q * 2 + 0]));
                f.y = fmaxf(0.f, fmaf(f.y, g_scale[kg + q * 2 + 1], g_shift[kg + q * 2 + 1]));
                __half2 h = __floats2half2_rn(f.x, f.y);
                ov[q] = *(uint32_t*)&h;
            }
            *(uint4*)&sAh[r * 72 + kq * 8] = outv;
        }
        __syncthreads();

        #pragma unroll
        for (int ks = 0; ks < 4; ks++) {
            int k0 = ks * 16;
            uint32_t Ah[4][4], Wh[2][4], Wl[2][4];
            #pragma unroll
            for (int mt = 0; mt < 4; mt++) {
                uint32_t off = (uint32_t)((mt * 16 * 72 + k0) * 2);
                ldsm4(Ah[mt], aAddrH + off);
            }
            #pragma unroll
            for (int ng = 0; ng < 2; ng++) {
                uint32_t off = (uint32_t)((k0 * 136 + ng * 16) * 2);
                ldsm4t(Wh[ng], wAddrH + off);
                ldsm4t(Wl[ng], wAddrL + off);
            }
            #pragma unroll
            for (int mt = 0; mt < 4; mt++)
                #pragma unroll
                for (int nt = 0; nt < 4; nt++) {
                    int ng = nt >> 1, s = (nt & 1) * 2;
                    mma_f16(acc[mt][nt], Ah[mt], Wh[ng][s], Wh[ng][s + 1]);
                    mma_f16(acc[mt][nt], Ah[mt], Wl[ng][s], Wl[ng][s + 1]);
                }
        }
        __syncthreads();
    }

    #pragma unroll
    for (int mt = 0; mt < 4; mt++) {
        int r0 = m0 + m_warp + mt * 16 + (lane >> 2);
        #pragma unroll
        for (int nt = 0; nt < 4; nt++) {
            int col = n_warp + nt * 8 + (lane & 3) * 2;
            float b0 = bias[col], b1 = bias[col + 1];
            if (r0 < M) {
                __half2 o = __floats2half2_rn(acc[mt][nt][0] + b0, acc[mt][nt][1] + b1);
                *(__half2*)(out16 + r0 * 128 + col) = o;
            }
            if (r0 + 8 < M) {
                __half2 o = __floats2half2_rn(acc[mt][nt][2] + b0, acc[mt][nt][3] + b1);
                *(__half2*)(out16 + (r0 + 8) * 128 + col) = o;
            }
        }
    }
}

// ---------------- SpMM: coalesced int2 edge load + shfl distribution, MLP=4 ----------------
__global__ __launch_bounds__(256) void k_spmm5(const uint4* __restrict__ h16,
                                               uint4* __restrict__ o16,
                                               float4* __restrict__ o32,
                                               int statSlot, int outHalf)
{
    __shared__ float ssum[DD];
    __shared__ float ssq[DD];
    int t = threadIdx.x;
    if (statSlot >= 0) {
        if (t < DD) { ssum[t] = 0.f; ssq[t] = 0.f; }
        __syncthreads();
    }
    int lane = t & 31;
    int hw = lane >> 4;       // half-warp id
    int sl = lane & 15;       // slot: covers cols 8*sl..8*sl+7
    int gw = (blockIdx.x * 256 + t) >> 5;
    int nw = (gridDim.x * 256) >> 5;

    float as[8] = {}, aq[8] = {};

    for (int r = gw; r < NN; r += nw) {
        int jb = g_rptr[r], je = g_rptr[r + 1];
        float acc[8] = {};
        for (int j0 = jb; j0 < je; j0 += 32) {
            int myj = j0 + lane;
            long long ev = 0;
            if (myj < je) ev = *(const long long*)&g_edge[myj];
            int cnt = min(32, je - j0);
            // groups of 8 edges: 4 per half-warp, 4 independent gathers in flight
            for (int i = 0; i < cnt; i += 8) {
                int cc[4]; float ww[4]; uint4 hv[4];
                #pragma unroll
                for (int u = 0; u < 4; u++) {
                    int idx = i + u * 2 + hw;
                    long long e_s = __shfl_sync(0xffffffffu, ev, idx & 31);
                    bool ok = (idx < cnt);
                    int2 e = *(int2*)&e_s;
                    cc[u] = ok ? e.x : 0;
                    ww[u] = ok ? __int_as_float(e.y) : 0.f;
                }
                #pragma unroll
                for (int u = 0; u < 4; u++)
                    hv[u] = h16[cc[u] * 16 + sl];
                #pragma unroll
                for (int u = 0; u < 4; u++) {
                    float2 f0 = __half22float2(*(__half2*)&hv[u].x);
                    float2 f1 = __half22float2(*(__half2*)&hv[u].y);
                    float2 f2 = __half22float2(*(__half2*)&hv[u].z);
                    float2 f3 = __half22float2(*(__half2*)&hv[u].w);
                    acc[0] = fmaf(ww[u], f0.x, acc[0]);
                    acc[1] = fmaf(ww[u], f0.y, acc[1]);
                    acc[2] = fmaf(ww[u], f1.x, acc[2]);
                    acc[3] = fmaf(ww[u], f1.y, acc[3]);
                    acc[4] = fmaf(ww[u], f2.x, acc[4]);
                    acc[5] = fmaf(ww[u], f2.y, acc[5]);
                    acc[6] = fmaf(ww[u], f3.x, acc[6]);
                    acc[7] = fmaf(ww[u], f3.y, acc[7]);
                }
            }
        }
        // combine half-warps
        #pragma unroll
        for (int k = 0; k < 8; k++)
            acc[k] += __shfl_xor_sync(0xffffffffu, acc[k], 16);
        if (lane < 16) {
            if (outHalf) {
                uint4 ov;
                uint32_t* o = &ov.x;
                #pragma unroll
                for (int q = 0; q < 4; q++) {
                    __half2 h = __floats2half2_rn(acc[q * 2], acc[q * 2 + 1]);
                    o[q] = *(uint32_t*)&h;
                }
                o16[r * 16 + sl] = ov;
            } else {
                o32[r * 32 + sl * 2 + 0] = make_float4(acc[0], acc[1], acc[2], acc[3]);
                o32[r * 32 + sl * 2 + 1] = make_float4(acc[4], acc[5], acc[6], acc[7]);
            }
            if (statSlot >= 0) {
                #pragma unroll
                for (int k = 0; k < 8; k++) {
                    as[k] += acc[k];
                    aq[k] = fmaf(acc[k], acc[k], aq[k]);
                }
            }
        }
    }
    if (statSlot >= 0) {
        if (lane < 16) {
            #pragma unroll
            for (int k = 0; k < 8; k++) {
                atomicAdd(&ssum[sl * 8 + k], as[k]);
                atomicAdd(&ssq[sl * 8 + k], aq[k]);
            }
        }
        __syncthreads();
        if (t < DD) {
            atomicAdd(&g_sum[statSlot][t], ssum[t]);
            atomicAdd(&g_sq[statSlot][t], ssq[t]);
        }
    }
}

// ---------------- BN params ----------------
__global__ void k_bnparams(const float* __restrict__ gamma, const float* __restrict__ beta,
                           int slot) {
    int t = threadIdx.x;
    if (t >= DD) return;
    float invn = 1.0f / (float)NN;
    float m = g_sum[slot][t] * invn;
    float v = g_sq[slot][t] * invn - m * m;
    float sc = gamma[t] * rsqrtf(v + BN_EPS);
    g_scale[t] = sc;
    g_shift[t] = beta[t] - sc * m;
}

// ---------------- launch ----------------
extern "C" void kernel_launch(void* const* d_in, const int* in_sizes, int n_in,
                              void* d_out, int out_size) {
    (void)in_sizes; (void)n_in; (void)out_size;
    const float* x  = (const float*)d_in[0];
    const float* ew = (const float*)d_in[1];
    const float* W0 = (const float*)d_in[2];
    const float* b0 = (const float*)d_in[3];
    const float* g0 = (const float*)d_in[4];
    const float* be0= (const float*)d_in[5];
    const float* W1 = (const float*)d_in[6];
    const float* b1 = (const float*)d_in[7];
    const float* g1 = (const float*)d_in[8];
    const float* be1= (const float*)d_in[9];
    const float* W2 = (const float*)d_in[10];
    const float* b2 = (const float*)d_in[11];
    const int* row  = (const int*)d_in[12];
    const int* col  = (const int*)d_in[13];
    float* out = (float*)d_out;

    __half *pH, *pA;
    cudaGetSymbolAddress((void**)&pH, g_h16);
    cudaGetSymbolAddress((void**)&pA, g_a16);

    static cudaStream_t s_csr = nullptr;
    static cudaEvent_t e_fork = nullptr, e_join = nullptr;
    if (s_csr == nullptr) {
        cudaStreamCreateWithFlags(&s_csr, cudaStreamNonBlocking);
        cudaEventCreateWithFlags(&e_fork, cudaEventDisableTiming);
        cudaEventCreateWithFlags(&e_join, cudaEventDisableTiming);
        cudaFuncSetAttribute(k_gemm_tc, cudaFuncAttributeMaxDynamicSharedMemorySize, GEMM_SMEM);
        cudaFuncSetAttribute(k_gemm_tc_h, cudaFuncAttributeMaxDynamicSharedMemorySize, GEMMH_SMEM);
    }

    int gb256_N = (NN + 255) / 256;
    int gb256_E = (EE + 255) / 256;
    int gemm_blocks = (NN + 127) / 128;
    int spmm_blocks = 1184;

    // fork: CSR build + stats zero overlap with W prep + layer-0 GEMM
    cudaEventRecord(e_fork, 0);
    cudaStreamWaitEvent(s_csr, e_fork, 0);
    k_zero_cnt<<<gb256_N, 256, 0, s_csr>>>();
    k_count<<<gb256_E, 256, 0, s_csr>>>(row);
    k_scan1<<<NB_SCAN, 1024, 0, s_csr>>>();
    k_scan2<<<1, 128, 0, s_csr>>>(NB_SCAN);
    k_scan3<<<gb256_N, 256, 0, s_csr>>>();
    k_fill<<<gb256_E, 256, 0, s_csr>>>(row, col, ew);
    cudaEventRecord(e_join, s_csr);

    // main stream: layer 0 GEMM (fp32 x, 3-term)
    k_wprep<<<3 * 128, 128>>>(W0, W1, W2);
    k_gemm_tc<<<gemm_blocks, 256, GEMM_SMEM>>>(x, 0, b0, pH, NN);

    // join CSR before SpMM
    cudaStreamWaitEvent(0, e_join, 0);

    k_spmm5<<<spmm_blocks, 256>>>((const uint4*)pH, (uint4*)pA, nullptr, 0, 1);
    k_bnparams<<<1, 128>>>(g0, be0, 0);

    // layer 1
    k_gemm_tc_h<<<gemm_blocks, 256, GEMMH_SMEM>>>(pA, 1, b1, pH, NN);
    k_spmm5<<<spmm_blocks, 256>>>((const uint4*)pH, (uint4*)pA, nullptr, 1, 1);
    k_bnparams<<<1, 128>>>(g1, be1, 1);

    // layer 2 (no stats, fp32 out)
    k_gemm_tc_h<<<gemm_blocks, 256, GEMMH_SMEM>>>(pA, 2, b2, pH, NN);
    k_spmm5<<<spmm_blocks, 256>>>((const uint4*)pH, nullptr, (float4*)out, -1, 0);
}